// round 13
// baseline (speedup 1.0000x reference)
#include <cuda_runtime.h>
#include <cuda_fp16.h>
#include <cstdint>

// Problem constants
#define NT 4096        // B*S tokens
#define DM 512         // d_model
#define DF 2048        // d_ff
#define NE 8           // experts
#define NP 8192        // token-expert pairs
#define NPPAD 10240    // NP + NE*256 padding (expert segments 256-aligned)
#define RBLK  (NPPAD / 256)   // 40 row blocks

// Tile blocks (pre-swizzled, contiguous for cp.async.bulk)
#define ABLK 32768     // 256 rows x 128B (one A tile-chunk)
#define BBLK 16384     // 128 rows x 128B (one B-limb tile-chunk)
#define TILE_A      32768
#define TILE_B_HALF 16384
#define STAGE_BYTES 65536     // A(32K) + Bhi(16K) + Blo(16K)
#define WSCALE 64.0f
#define INV_WSCALE (1.0f / 64.0f)

// ---------------------------------------------------------------- scratch
__device__ int   g_count[NE];
__device__ int   g_off[NE];
__device__ int   g_fill[NE];
__device__ int   g_tok[NPPAD];
__device__ float g_coef[NPPAD];
__device__ int   g_pairpos[NP];

// Weights, tiled: [e][nblk][chunk][16384B swizzled block]
__device__ __align__(128) unsigned char g_wiT_hi[(size_t)NE * 16 * 8 * BBLK];
__device__ __align__(128) unsigned char g_wiT_lo[(size_t)NE * 16 * 8 * BBLK];
__device__ __align__(128) unsigned char g_woT_hi[(size_t)NE * 4 * 32 * BBLK];
__device__ __align__(128) unsigned char g_woT_lo[(size_t)NE * 4 * 32 * BBLK];
// Activations, tiled: [rowblk][chunk][32768B swizzled block]
__device__ __align__(128) unsigned char g_Xg[(size_t)RBLK * 8 * ABLK];
__device__ __align__(128) unsigned char g_H[(size_t)RBLK * 32 * ABLK];
__device__ __align__(128) float g_Y[(size_t)NPPAD * DM];

// ---------------------------------------------------------------- helpers
__device__ __forceinline__ uint32_t smem_u32(const void* p) {
    uint32_t a;
    asm("{ .reg .u64 t; cvta.to.shared.u64 t, %1; cvt.u32.u64 %0, t; }" : "=r"(a) : "l"(p));
    return a;
}
#define LDSM4(R0, R1, R2, R3, ADDR)                                                \
    asm volatile("ldmatrix.sync.aligned.m8n8.x4.shared.b16 {%0,%1,%2,%3}, [%4];"   \
        : "=r"(R0), "=r"(R1), "=r"(R2), "=r"(R3) : "r"(ADDR))

__device__ __forceinline__ void mma16816(float* c, const uint32_t* a, const uint32_t* b) {
    asm volatile(
        "mma.sync.aligned.m16n8k16.row.col.f32.f16.f16.f32 "
        "{%0,%1,%2,%3}, {%4,%5,%6,%7}, {%8,%9}, {%0,%1,%2,%3};"
        : "+f"(c[0]), "+f"(c[1]), "+f"(c[2]), "+f"(c[3])
        : "r"(a[0]), "r"(a[1]), "r"(a[2]), "r"(a[3]), "r"(b[0]), "r"(b[1]));
}

#define SWZ(x) ((x) ^ (((x) >> 3) & 0x70))

#define MBAR_INIT(a, c) asm volatile("mbarrier.init.shared.b64 [%0], %1;" :: "r"(a), "r"((uint32_t)(c)) : "memory")
#define MBAR_EXPECT_TX(a, b) asm volatile("mbarrier.arrive.expect_tx.shared.b64 _, [%0], %1;" :: "r"(a), "r"((uint32_t)(b)) : "memory")
#define MBAR_WAIT(mbar, parity) do {                                              \
    uint32_t _m = (mbar), _p = (parity), _d;                                      \
    asm volatile("{ .reg .pred p; mbarrier.try_wait.parity.acquire.cta.shared::cta.b64 p, [%1], %2; selp.b32 %0, 1, 0, p; }" \
        : "=r"(_d) : "r"(_m), "r"(_p) : "memory");                                \
    if (!_d) {                                                                    \
        asm volatile("{ .reg .pred P1; WL_%=: mbarrier.try_wait.parity.acquire.cta.shared::cta.b64 P1, [%0], %1, 0x989680; @P1 bra.uni WD_%=; bra.uni WL_%=; WD_%=: }" \
            :: "r"(_m), "r"(_p) : "memory");                                      \
    }                                                                             \
} while (0)
#define BULK_G2S(dst, src, bytes, mbar)                                           \
    asm volatile("cp.async.bulk.shared::cluster.global.mbarrier::complete_tx::bytes [%0], [%1], %2, [%3];" \
        :: "r"(dst), "l"(src), "r"((uint32_t)(bytes)), "r"(mbar) : "memory")

__device__ __forceinline__ uint32_t pack2h(__half a, __half b) {
    __half2 t = __halves2half2(a, b);
    return *reinterpret_cast<uint32_t*>(&t);
}
__device__ __forceinline__ void split1h(float v, __half& h, __half& l) {
    h = __float2half(v);
    l = __float2half(v - __half2float(h));
}

// ---------------------------------------------------------------- routing
__global__ void route_kernel(const int* __restrict__ eidx, const float* __restrict__ prob) {
    __shared__ int s_cnt[NE];
    const int tid = threadIdx.x;
    if (tid < NE) s_cnt[tid] = 0;
    __syncthreads();
    for (int p = tid; p < NP; p += blockDim.x) atomicAdd(&s_cnt[eidx[p]], 1);
    __syncthreads();
    if (tid == 0) {
        int start = 0;
        for (int e = 0; e < NE; e++) {
            g_count[e] = s_cnt[e]; g_off[e] = start; g_fill[e] = start;
            start += (s_cnt[e] + 255) & ~255;   // 256-aligned segments
        }
    }
    for (int i = tid; i < NPPAD; i += blockDim.x) { g_tok[i] = 0; g_coef[i] = 0.f; }
    __syncthreads();
    for (int p = tid; p < NP; p += blockDim.x) {
        const int e = eidx[p];
        const int pos = atomicAdd(&g_fill[e], 1);
        const float df = (p & 1) ? 0.25f : 0.5f;
        g_pairpos[p] = pos;
        g_tok[pos]   = p >> 1;
        g_coef[pos]  = df * prob[p];
    }
}

// ------------------------- gather activations -> fp16, tiled+swizzled blocks
__global__ void split_x_kernel(const float* __restrict__ X) {
    const int i = blockIdx.x * 256 + threadIdx.x;       // over NPPAD * (DM/4)
    if (i >= NPPAD * (DM / 4)) return;
    const int row = i / (DM / 4);
    const int c4  = i % (DM / 4);                       // 16B unit in source row
    const float4 v = reinterpret_cast<const float4*>(X + (size_t)g_tok[row] * DM)[c4];
    const uint2 o = make_uint2(pack2h(__float2half(v.x), __float2half(v.y)),
                               pack2h(__float2half(v.z), __float2half(v.w)));
    const int blk = row >> 8, rowin = row & 255;
    const int ch  = c4 >> 4;                            // 64-col chunk
    const uint32_t byte = SWZ((uint32_t)(rowin * 128 + (c4 & 15) * 8));
    *reinterpret_cast<uint2*>(g_Xg + ((size_t)blk * 8 + ch) * ABLK + byte) = o;
}

// --------- transpose + scale(x64) + split weights -> tiled+swizzled limb blocks
// src [e][R][C] fp32 -> limbs [e][n/128][k/64][SWZ((n%128)*128 + (k%64)*2)]
__global__ void transpose_split_kernel(const float* __restrict__ src, int R, int C, int which) {
    unsigned char* dhi = which ? g_woT_hi : g_wiT_hi;
    unsigned char* dlo = which ? g_woT_lo : g_wiT_lo;
    const int e = blockIdx.z;
    const int NBLKn = C / 128, NCHk = R / 64;
    const float* s = src + (size_t)e * R * C;

    __shared__ float t[64][65];
    const int c0 = blockIdx.x * 64, r0 = blockIdx.y * 64;
    const int tid = threadIdx.x;

    const int lr = tid >> 4;          // 0..15
    const int lc = (tid & 15) * 4;    // 0..60
#pragma unroll
    for (int it = 0; it < 4; it++) {
        const int r = it * 16 + lr;
        const float4 v = *reinterpret_cast<const float4*>(s + (size_t)(r0 + r) * C + c0 + lc);
        t[lc + 0][r] = v.x; t[lc + 1][r] = v.y; t[lc + 2][r] = v.z; t[lc + 3][r] = v.w;
    }
    __syncthreads();

    const int oc = tid >> 2;          // 0..63  (output n within 64-tile)
    const int rs = (tid & 3) * 16;    // k start 0,16,32,48
    uint32_t hw[8], lw[8];
#pragma unroll
    for (int q = 0; q < 8; q++) {
        const float v0 = t[oc][rs + 2 * q]     * WSCALE;
        const float v1 = t[oc][rs + 2 * q + 1] * WSCALE;
        __half h0, l0, h1, l1;
        split1h(v0, h0, l0); split1h(v1, h1, l1);
        hw[q] = pack2h(h0, h1); lw[q] = pack2h(l0, l1);
    }
    const int n = c0 + oc, k = r0 + rs;
    const size_t boff = (((size_t)e * NBLKn + (n >> 7)) * NCHk + (k >> 6)) * BBLK;
    const int nin = n & 127, kin = k & 63;
    const uint32_t b0 = SWZ((uint32_t)(nin * 128 + kin * 2));
    const uint32_t b1 = SWZ((uint32_t)(nin * 128 + kin * 2 + 16));
    *reinterpret_cast<uint4*>(dhi + boff + b0) = make_uint4(hw[0], hw[1], hw[2], hw[3]);
    *reinterpret_cast<uint4*>(dhi + boff + b1) = make_uint4(hw[4], hw[5], hw[6], hw[7]);
    *reinterpret_cast<uint4*>(dlo + boff + b0) = make_uint4(lw[0], lw[1], lw[2], lw[3]);
    *reinterpret_cast<uint4*>(dlo + boff + b1) = make_uint4(lw[4], lw[5], lw[6], lw[7]);
}

// ------------------------------------------------- HMMA GEMM (both layers)
// MODE 0: H = relu(Xg @ wiT'^T)/64      [K=DM, N=DF] -> fp16 tiled blocks
// MODE 1: Y = (coef/64) * (H @ woT'^T)  [K=DF, N=DM] -> fp32
// CTA: 256 M x 128 N, 512 threads = 16 warps in 4(M) x 4(N), warp tile 64x32.
// 2-product weights hi+lo; bulk-async loads, mbarrier-paced, 2 stages.
template <int MODE>
__global__ __launch_bounds__(512)
void gemm_mma() {
    constexpr int NC = (MODE == 0) ? (DM / 64) : (DF / 64);

    const int e = blockIdx.z;
    const int cnt = g_count[e];
    const int mbase = blockIdx.y * 256;
    if (mbase >= cnt) return;
    const int off = g_off[e];
    const int nbase = blockIdx.x * 128;
    const int tid = threadIdx.x;
    const int lid = tid & 31;
    const int wid = tid >> 5;
    const int wm = wid >> 2;      // 0..3 -> 64-row slab
    const int wn = wid & 3;       // 0..3 -> 32-col slab

    extern __shared__ char dynsmem[];
    const uint32_t raw  = smem_u32(dynsmem);
    const uint32_t base = (raw + 1023) & ~1023u;
    __shared__ __align__(8) uint64_t s_mbar[2];
    const uint32_t mb0 = smem_u32(&s_mbar[0]);
    const uint32_t mb1 = smem_u32(&s_mbar[1]);

    if (tid == 0) { MBAR_INIT(mb0, 1); MBAR_INIT(mb1, 1); }
    __syncthreads();

    const int ablk = (off + mbase) >> 8;
    const unsigned char* Asrc = (MODE == 0)
        ? (g_Xg + (size_t)ablk * 8  * ABLK)
        : (g_H  + (size_t)ablk * 32 * ABLK);
    const unsigned char* Bhi = (MODE == 0)
        ? (g_wiT_hi + (((size_t)e * 16 + (nbase >> 7)) * 8)  * BBLK)
        : (g_woT_hi + (((size_t)e * 4  + (nbase >> 7)) * 32) * BBLK);
    const unsigned char* Blo = (MODE == 0)
        ? (g_wiT_lo + (((size_t)e * 16 + (nbase >> 7)) * 8)  * BBLK)
        : (g_woT_lo + (((size_t)e * 4  + (nbase >> 7)) * 32) * BBLK);

    auto issue = [&](int c) {
        const uint32_t mb = (c & 1) ? mb1 : mb0;
        const uint32_t tb = base + (c & 1) * STAGE_BYTES;
        MBAR_EXPECT_TX(mb, STAGE_BYTES);
        BULK_G2S(tb,                 Asrc + (size_t)c * ABLK, ABLK, mb);
        BULK_G2S(tb + TILE_A,        Bhi  + (size_t)c * BBLK, BBLK, mb);
        BULK_G2S(tb + TILE_A + TILE_B_HALF, Blo + (size_t)c * BBLK, BBLK, mb);
    };

    float acc[4][4][4];
#pragma unroll
    for (int f = 0; f < 4; f++)
#pragma unroll
        for (int j = 0; j < 4; j++)
#pragma unroll
            for (int q = 0; q < 4; q++) acc[f][j][q] = 0.f;

    const int bq  = (lid & 7) | ((lid >> 4) << 3);   // B: n row within 16-group
    const int bkh = ((lid >> 3) & 1) * 16;           // B: k-half byte offset
    const int ar  = lid & 15;                        // A: m row within 16-group
    const int akh = (lid >> 4) * 16;                 // A: k-half byte offset

    if (tid == 0) { issue(0); issue(1); }

    for (int c = 0; c < NC; c++) {
        MBAR_WAIT((c & 1) ? mb1 : mb0, (c >> 1) & 1);

        const uint32_t tb   = base + (c & 1) * STAGE_BYTES;
        const uint32_t pA   = tb;
        const uint32_t pBhi = tb + TILE_A;
        const uint32_t pBlo = tb + TILE_A + TILE_B_HALF;

#pragma unroll
        for (int s = 0; s < 4; s++) {
            const int kb = s * 32;                   // byte offset of k16 step
            uint32_t bh[4][2], bl[4][2];
#pragma unroll
            for (int P = 0; P < 2; P++) {            // 32 n-cols = 2 x 16 rows
                const uint32_t a = SWZ((wn * 32 + P * 16 + bq) * 128 + kb + bkh);
                LDSM4(bh[2 * P][0], bh[2 * P][1], bh[2 * P + 1][0], bh[2 * P + 1][1], pBhi + a);
                LDSM4(bl[2 * P][0], bl[2 * P][1], bl[2 * P + 1][0], bl[2 * P + 1][1], pBlo + a);
            }
#pragma unroll
            for (int f = 0; f < 4; f++) {
                uint32_t av[4];
                const uint32_t a = SWZ((wm * 64 + f * 16 + ar) * 128 + kb + akh);
                LDSM4(av[0], av[1], av[2], av[3], pA + a);
#pragma unroll
                for (int j = 0; j < 4; j++) mma16816(acc[f][j], av, bh[j]);
#pragma unroll
                for (int j = 0; j < 4; j++) mma16816(acc[f][j], av, bl[j]);
            }
        }
        __syncthreads();                      // all warps done with stage c&1
        if (tid == 0 && c + 2 < NC) issue(c + 2);
    }

    // ------------------------------------------------------------ epilogue
#pragma unroll
    for (int f = 0; f < 4; f++) {
        const int rib0 = wm * 64 + f * 16 + (lid >> 2);      // row in 256-block
#pragma unroll
        for (int h = 0; h < 2; h++) {
            const int rib = rib0 + h * 8;
            const int r = mbase + rib;
            if (r < cnt) {
                if (MODE == 0) {
                    // H tiled: [ablk][col/64][SWZ(rib*128 + (col%64)*2)]
                    const int ch = (nbase >> 6) + (wn >> 1);
                    unsigned char* Hb = g_H + ((size_t)ablk * 32 + ch) * ABLK;
#pragma unroll
                    for (int j = 0; j < 4; j++) {
                        const float v0 = fmaxf(acc[f][j][2 * h], 0.f) * INV_WSCALE;
                        const float v1 = fmaxf(acc[f][j][2 * h + 1], 0.f) * INV_WSCALE;
                        const uint32_t byte = SWZ((uint32_t)(rib * 128 + (wn & 1) * 64 + (lid & 3) * 4 + j * 16));
                        *reinterpret_cast<uint32_t*>(Hb + byte) = pack2h(__float2half(v0), __float2half(v1));
                    }
                } else {
                    const float cf = g_coef[off + r] * INV_WSCALE;
                    const int colb = nbase + wn * 32 + (lid & 3) * 2;
                    float* Yp = g_Y + (size_t)(off + r) * DM + colb;
#pragma unroll
                    for (int j = 0; j < 4; j++) {
                        float2 v;
                        v.x = cf * acc[f][j][2 * h];
                        v.y = cf * acc[f][j][2 * h + 1];
                        *reinterpret_cast<float2*>(Yp + j * 8) = v;
                    }
                }
            }
        }
    }
}

// ---------------------------------------------------- finalize: combine + where
__global__ void finalize_kernel(const float* __restrict__ X, float* __restrict__ out) {
    const int i = blockIdx.x * blockDim.x + threadIdx.x;
    if (i >= NT * DM / 4) return;
    const int t = i / (DM / 4);
    const int d4 = i % (DM / 4);
    const int p0 = g_pairpos[2 * t];
    const int p1 = g_pairpos[2 * t + 1];
    const float4 y0 = *reinterpret_cast<const float4*>(g_Y + (size_t)p0 * DM + d4 * 4);
    const float4 y1 = *reinterpret_cast<const float4*>(g_Y + (size_t)p1 * DM + d4 * 4);
    const float4 xv = reinterpret_cast<const float4*>(X)[i];
    float4 s, o;
    s.x = y0.x + y1.x; s.y = y0.y + y1.y; s.z = y0.z + y1.z; s.w = y0.w + y1.w;
    o.x = (s.x != 0.f) ? s.x : xv.x;
    o.y = (s.y != 0.f) ? s.y : xv.y;
    o.z = (s.z != 0.f) ? s.z : xv.z;
    o.w = (s.w != 0.f) ? s.w : xv.w;
    reinterpret_cast<float4*>(out)[i] = o;
}

extern "C" void kernel_launch(void* const* d_in, const int* in_sizes, int n_in,
                              void* d_out, int out_size) {
    const float* hs   = (const float*)d_in[0];   // [4096, 512]
    const float* prob = (const float*)d_in[1];   // [4096, 2]
    const float* wi   = (const float*)d_in[2];   // [8, 512, 2048]
    const float* wo   = (const float*)d_in[3];   // [8, 2048, 512]
    const int*   eidx = (const int*)d_in[4];     // [4096, 2]
    float* out = (float*)d_out;

    const int SMEM = 2 * STAGE_BYTES + 1024;     // 132096 B
    cudaFuncSetAttribute(gemm_mma<0>, cudaFuncAttributeMaxDynamicSharedMemorySize, SMEM);
    cudaFuncSetAttribute(gemm_mma<1>, cudaFuncAttributeMaxDynamicSharedMemorySize, SMEM);

    route_kernel<<<1, 256>>>(eidx, prob);
    split_x_kernel<<<(NPPAD * (DM / 4) + 255) / 256, 256>>>(hs);
    transpose_split_kernel<<<dim3(DF / 64, DM / 64, NE), 256>>>(wi, DM, DF, 0);
    transpose_split_kernel<<<dim3(DM / 64, DF / 64, NE), 256>>>(wo, DF, DM, 1);

    gemm_mma<0><<<dim3(DF / 128, RBLK, NE), 512, SMEM>>>();
    gemm_mma<1><<<dim3(DM / 128, RBLK, NE), 512, SMEM>>>();

    finalize_kernel<<<(NT * DM / 4 + 255) / 256, 256>>>(hs, out);
}

// round 14
// speedup vs baseline: 1.0018x; 1.0018x over previous
#include <cuda_runtime.h>
#include <cuda_fp16.h>
#include <cstdint>

// Problem constants
#define NT 4096        // B*S tokens
#define DM 512         // d_model
#define DF 2048        // d_ff
#define NE 8           // experts
#define NP 8192        // token-expert pairs
#define NPPAD 10240    // NP + NE*256 padding (expert segments 256-aligned)
#define RBLK  (NPPAD / 256)   // 40 row blocks

// Tile blocks (pre-swizzled, contiguous for cp.async.bulk)
#define ABLK 32768     // 256 rows x 128B (one A tile-chunk)
#define BBLK 16384     // 128 rows x 128B (one B-limb tile-chunk)
#define TILE_A      32768
#define TILE_B_HALF 16384
#define STAGE_BYTES 65536     // A(32K) + Bhi(16K) + Blo(16K)
#define NSTAGE 3
#define WSCALE 64.0f
#define INV_WSCALE (1.0f / 64.0f)

// ---------------------------------------------------------------- scratch
__device__ int   g_count[NE];
__device__ int   g_off[NE];
__device__ int   g_fill[NE];
__device__ int   g_tok[NPPAD];
__device__ float g_coef[NPPAD];
__device__ int   g_pairpos[NP];

// Weights, tiled: [e][nblk][chunk][16384B swizzled block]
__device__ __align__(128) unsigned char g_wiT_hi[(size_t)NE * 16 * 8 * BBLK];
__device__ __align__(128) unsigned char g_wiT_lo[(size_t)NE * 16 * 8 * BBLK];
__device__ __align__(128) unsigned char g_woT_hi[(size_t)NE * 4 * 32 * BBLK];
__device__ __align__(128) unsigned char g_woT_lo[(size_t)NE * 4 * 32 * BBLK];
// Activations, tiled: [rowblk][chunk][32768B swizzled block]
__device__ __align__(128) unsigned char g_Xg[(size_t)RBLK * 8 * ABLK];
__device__ __align__(128) unsigned char g_H[(size_t)RBLK * 32 * ABLK];
__device__ __align__(128) float g_Y[(size_t)NPPAD * DM];

// ---------------------------------------------------------------- helpers
__device__ __forceinline__ uint32_t smem_u32(const void* p) {
    uint32_t a;
    asm("{ .reg .u64 t; cvta.to.shared.u64 t, %1; cvt.u32.u64 %0, t; }" : "=r"(a) : "l"(p));
    return a;
}
#define LDSM4(R0, R1, R2, R3, ADDR)                                                \
    asm volatile("ldmatrix.sync.aligned.m8n8.x4.shared.b16 {%0,%1,%2,%3}, [%4];"   \
        : "=r"(R0), "=r"(R1), "=r"(R2), "=r"(R3) : "r"(ADDR))

__device__ __forceinline__ void mma16816(float* c, const uint32_t* a, const uint32_t* b) {
    asm volatile(
        "mma.sync.aligned.m16n8k16.row.col.f32.f16.f16.f32 "
        "{%0,%1,%2,%3}, {%4,%5,%6,%7}, {%8,%9}, {%0,%1,%2,%3};"
        : "+f"(c[0]), "+f"(c[1]), "+f"(c[2]), "+f"(c[3])
        : "r"(a[0]), "r"(a[1]), "r"(a[2]), "r"(a[3]), "r"(b[0]), "r"(b[1]));
}

#define SWZ(x) ((x) ^ (((x) >> 3) & 0x70))

#define MBAR_INIT(a, c) asm volatile("mbarrier.init.shared.b64 [%0], %1;" :: "r"(a), "r"((uint32_t)(c)) : "memory")
#define MBAR_EXPECT_TX(a, b) asm volatile("mbarrier.arrive.expect_tx.shared.b64 _, [%0], %1;" :: "r"(a), "r"((uint32_t)(b)) : "memory")
#define MBAR_WAIT(mbar, parity) do {                                              \
    uint32_t _m = (mbar), _p = (parity), _d;                                      \
    asm volatile("{ .reg .pred p; mbarrier.try_wait.parity.acquire.cta.shared::cta.b64 p, [%1], %2; selp.b32 %0, 1, 0, p; }" \
        : "=r"(_d) : "r"(_m), "r"(_p) : "memory");                                \
    if (!_d) {                                                                    \
        asm volatile("{ .reg .pred P1; WL_%=: mbarrier.try_wait.parity.acquire.cta.shared::cta.b64 P1, [%0], %1, 0x989680; @P1 bra.uni WD_%=; bra.uni WL_%=; WD_%=: }" \
            :: "r"(_m), "r"(_p) : "memory");                                      \
    }                                                                             \
} while (0)
#define BULK_G2S(dst, src, bytes, mbar)                                           \
    asm volatile("cp.async.bulk.shared::cluster.global.mbarrier::complete_tx::bytes [%0], [%1], %2, [%3];" \
        :: "r"(dst), "l"(src), "r"((uint32_t)(bytes)), "r"(mbar) : "memory")

__device__ __forceinline__ uint32_t pack2h(__half a, __half b) {
    __half2 t = __halves2half2(a, b);
    return *reinterpret_cast<uint32_t*>(&t);
}
__device__ __forceinline__ void split1h(float v, __half& h, __half& l) {
    h = __float2half(v);
    l = __float2half(v - __half2float(h));
}

// ---------------------------------------------------------------- routing
__global__ void route_kernel(const int* __restrict__ eidx, const float* __restrict__ prob) {
    __shared__ int s_cnt[NE];
    const int tid = threadIdx.x;
    if (tid < NE) s_cnt[tid] = 0;
    __syncthreads();
    for (int p = tid; p < NP; p += blockDim.x) atomicAdd(&s_cnt[eidx[p]], 1);
    __syncthreads();
    if (tid == 0) {
        int start = 0;
        for (int e = 0; e < NE; e++) {
            g_count[e] = s_cnt[e]; g_off[e] = start; g_fill[e] = start;
            start += (s_cnt[e] + 255) & ~255;   // 256-aligned segments
        }
    }
    for (int i = tid; i < NPPAD; i += blockDim.x) { g_tok[i] = 0; g_coef[i] = 0.f; }
    __syncthreads();
    for (int p = tid; p < NP; p += blockDim.x) {
        const int e = eidx[p];
        const int pos = atomicAdd(&g_fill[e], 1);
        const float df = (p & 1) ? 0.25f : 0.5f;
        g_pairpos[p] = pos;
        g_tok[pos]   = p >> 1;
        g_coef[pos]  = df * prob[p];
    }
}

// ------------------------- gather activations -> fp16, tiled+swizzled blocks
__global__ void split_x_kernel(const float* __restrict__ X) {
    const int i = blockIdx.x * 256 + threadIdx.x;       // over NPPAD * (DM/4)
    if (i >= NPPAD * (DM / 4)) return;
    const int row = i / (DM / 4);
    const int c4  = i % (DM / 4);                       // 16B unit in source row
    const float4 v = reinterpret_cast<const float4*>(X + (size_t)g_tok[row] * DM)[c4];
    const uint2 o = make_uint2(pack2h(__float2half(v.x), __float2half(v.y)),
                               pack2h(__float2half(v.z), __float2half(v.w)));
    const int blk = row >> 8, rowin = row & 255;
    const int ch  = c4 >> 4;                            // 64-col chunk
    const uint32_t byte = SWZ((uint32_t)(rowin * 128 + (c4 & 15) * 8));
    *reinterpret_cast<uint2*>(g_Xg + ((size_t)blk * 8 + ch) * ABLK + byte) = o;
}

// --------- transpose + scale(x64) + split weights -> tiled+swizzled limb blocks
// src [e][R][C] fp32 -> limbs [e][n/128][k/64][SWZ((n%128)*128 + (k%64)*2)]
__global__ void transpose_split_kernel(const float* __restrict__ src, int R, int C, int which) {
    unsigned char* dhi = which ? g_woT_hi : g_wiT_hi;
    unsigned char* dlo = which ? g_woT_lo : g_wiT_lo;
    const int e = blockIdx.z;
    const int NBLKn = C / 128, NCHk = R / 64;
    const float* s = src + (size_t)e * R * C;

    __shared__ float t[64][65];
    const int c0 = blockIdx.x * 64, r0 = blockIdx.y * 64;
    const int tid = threadIdx.x;

    const int lr = tid >> 4;          // 0..15
    const int lc = (tid & 15) * 4;    // 0..60
#pragma unroll
    for (int it = 0; it < 4; it++) {
        const int r = it * 16 + lr;
        const float4 v = *reinterpret_cast<const float4*>(s + (size_t)(r0 + r) * C + c0 + lc);
        t[lc + 0][r] = v.x; t[lc + 1][r] = v.y; t[lc + 2][r] = v.z; t[lc + 3][r] = v.w;
    }
    __syncthreads();

    const int oc = tid >> 2;          // 0..63  (output n within 64-tile)
    const int rs = (tid & 3) * 16;    // k start 0,16,32,48
    uint32_t hw[8], lw[8];
#pragma unroll
    for (int q = 0; q < 8; q++) {
        const float v0 = t[oc][rs + 2 * q]     * WSCALE;
        const float v1 = t[oc][rs + 2 * q + 1] * WSCALE;
        __half h0, l0, h1, l1;
        split1h(v0, h0, l0); split1h(v1, h1, l1);
        hw[q] = pack2h(h0, h1); lw[q] = pack2h(l0, l1);
    }
    const int n = c0 + oc, k = r0 + rs;
    const size_t boff = (((size_t)e * NBLKn + (n >> 7)) * NCHk + (k >> 6)) * BBLK;
    const int nin = n & 127, kin = k & 63;
    const uint32_t b0 = SWZ((uint32_t)(nin * 128 + kin * 2));
    const uint32_t b1 = SWZ((uint32_t)(nin * 128 + kin * 2 + 16));
    *reinterpret_cast<uint4*>(dhi + boff + b0) = make_uint4(hw[0], hw[1], hw[2], hw[3]);
    *reinterpret_cast<uint4*>(dhi + boff + b1) = make_uint4(hw[4], hw[5], hw[6], hw[7]);
    *reinterpret_cast<uint4*>(dlo + boff + b0) = make_uint4(lw[0], lw[1], lw[2], lw[3]);
    *reinterpret_cast<uint4*>(dlo + boff + b1) = make_uint4(lw[4], lw[5], lw[6], lw[7]);
}

// ------------------------------------------------- HMMA GEMM (both layers)
// MODE 0: H = relu(Xg @ wiT'^T)/64      [K=DM, N=DF] -> fp16 tiled blocks
// MODE 1: Y = (coef/64) * (H @ woT'^T)  [K=DF, N=DM] -> fp32
// CTA: 256 M x 128 N, 8 warps 4(M)x2(N), warp 64x64; 2-product weights hi+lo.
// Loads: cp.async.bulk of pre-swizzled blocks, mbarrier-paced, 3 stages.
template <int MODE>
__global__ __launch_bounds__(256)
void gemm_mma() {
    constexpr int NC = (MODE == 0) ? (DM / 64) : (DF / 64);

    const int e = blockIdx.z;
    const int cnt = g_count[e];
    const int mbase = blockIdx.y * 256;
    if (mbase >= cnt) return;
    const int off = g_off[e];
    const int nbase = blockIdx.x * 128;
    const int tid = threadIdx.x;
    const int lid = tid & 31;
    const int wid = tid >> 5;
    const int wm = wid >> 1;      // 0..3 -> 64-row slab
    const int wn = wid & 1;       // 0..1 -> 64-col slab

    extern __shared__ char dynsmem[];
    const uint32_t raw  = smem_u32(dynsmem);
    const uint32_t base = (raw + 1023) & ~1023u;
    __shared__ __align__(8) uint64_t s_mbar[NSTAGE];
    uint32_t mb[NSTAGE];
#pragma unroll
    for (int s = 0; s < NSTAGE; s++) mb[s] = smem_u32(&s_mbar[s]);

    if (tid == 0) {
#pragma unroll
        for (int s = 0; s < NSTAGE; s++) MBAR_INIT(mb[s], 1);
    }
    __syncthreads();

    const int ablk = (off + mbase) >> 8;
    const unsigned char* Asrc = (MODE == 0)
        ? (g_Xg + (size_t)ablk * 8  * ABLK)
        : (g_H  + (size_t)ablk * 32 * ABLK);
    const unsigned char* Bhi = (MODE == 0)
        ? (g_wiT_hi + (((size_t)e * 16 + (nbase >> 7)) * 8)  * BBLK)
        : (g_woT_hi + (((size_t)e * 4  + (nbase >> 7)) * 32) * BBLK);
    const unsigned char* Blo = (MODE == 0)
        ? (g_wiT_lo + (((size_t)e * 16 + (nbase >> 7)) * 8)  * BBLK)
        : (g_woT_lo + (((size_t)e * 4  + (nbase >> 7)) * 32) * BBLK);

    auto issue = [&](int c) {
        const int st = c % NSTAGE;
        const uint32_t m = mb[st];
        const uint32_t tb = base + st * STAGE_BYTES;
        MBAR_EXPECT_TX(m, STAGE_BYTES);
        BULK_G2S(tb,                        Asrc + (size_t)c * ABLK, ABLK, m);
        BULK_G2S(tb + TILE_A,               Bhi  + (size_t)c * BBLK, BBLK, m);
        BULK_G2S(tb + TILE_A + TILE_B_HALF, Blo  + (size_t)c * BBLK, BBLK, m);
    };

    float acc[4][8][4];
#pragma unroll
    for (int f = 0; f < 4; f++)
#pragma unroll
        for (int j = 0; j < 8; j++)
#pragma unroll
            for (int q = 0; q < 4; q++) acc[f][j][q] = 0.f;

    const int bq  = (lid & 7) | ((lid >> 4) << 3);   // B: n row within 16-group
    const int bkh = ((lid >> 3) & 1) * 16;           // B: k-half byte offset
    const int ar  = lid & 15;                        // A: m row within 16-group
    const int akh = (lid >> 4) * 16;                 // A: k-half byte offset

    if (tid == 0) { issue(0); issue(1); issue(2); }  // NC >= 8 always

    for (int c = 0; c < NC; c++) {
        const int st = c % NSTAGE;
        MBAR_WAIT(mb[st], (c / NSTAGE) & 1);

        const uint32_t tb   = base + st * STAGE_BYTES;
        const uint32_t pA   = tb;
        const uint32_t pBhi = tb + TILE_A;
        const uint32_t pBlo = tb + TILE_A + TILE_B_HALF;

#pragma unroll
        for (int s = 0; s < 4; s++) {
            const int kb = s * 32;                   // byte offset of k16 step
            uint32_t bh[8][2], bl[8][2];
#pragma unroll
            for (int P = 0; P < 4; P++) {            // 64 n-cols = 4 x 16 rows
                const uint32_t a = SWZ((wn * 64 + P * 16 + bq) * 128 + kb + bkh);
                LDSM4(bh[2 * P][0], bh[2 * P][1], bh[2 * P + 1][0], bh[2 * P + 1][1], pBhi + a);
                LDSM4(bl[2 * P][0], bl[2 * P][1], bl[2 * P + 1][0], bl[2 * P + 1][1], pBlo + a);
            }
#pragma unroll
            for (int f = 0; f < 4; f++) {
                uint32_t av[4];
                const uint32_t a = SWZ((wm * 64 + f * 16 + ar) * 128 + kb + akh);
                LDSM4(av[0], av[1], av[2], av[3], pA + a);
#pragma unroll
                for (int j = 0; j < 8; j++) mma16816(acc[f][j], av, bh[j]);
#pragma unroll
                for (int j = 0; j < 8; j++) mma16816(acc[f][j], av, bl[j]);
            }
        }
        __syncthreads();                      // all warps done with stage st
        if (tid == 0 && c + NSTAGE < NC) issue(c + NSTAGE);
    }

    // ------------------------------------------------------------ epilogue
#pragma unroll
    for (int f = 0; f < 4; f++) {
        const int rib0 = wm * 64 + f * 16 + (lid >> 2);      // row in 256-block
#pragma unroll
        for (int h = 0; h < 2; h++) {
            const int rib = rib0 + h * 8;
            const int r = mbase + rib;
            if (r < cnt) {
                if (MODE == 0) {
                    // H tiled: [ablk][col/64][SWZ(rib*128 + (col%64)*2)]
                    const int ch = (nbase >> 6) + wn;
                    unsigned char* Hb = g_H + ((size_t)ablk * 32 + ch) * ABLK;
#pragma unroll
                    for (int j = 0; j < 8; j++) {
                        const float v0 = fmaxf(acc[f][j][2 * h], 0.f) * INV_WSCALE;
                        const float v1 = fmaxf(acc[f][j][2 * h + 1], 0.f) * INV_WSCALE;
                        const uint32_t byte = SWZ((uint32_t)(rib * 128 + (lid & 3) * 4 + j * 16));
                        *reinterpret_cast<uint32_t*>(Hb + byte) = pack2h(__float2half(v0), __float2half(v1));
                    }
                } else {
                    const float cf = g_coef[off + r] * INV_WSCALE;
                    const int colb = nbase + wn * 64 + (lid & 3) * 2;
                    float* Yp = g_Y + (size_t)(off + r) * DM + colb;
#pragma unroll
                    for (int j = 0; j < 8; j++) {
                        float2 v;
                        v.x = cf * acc[f][j][2 * h];
                        v.y = cf * acc[f][j][2 * h + 1];
                        *reinterpret_cast<float2*>(Yp + j * 8) = v;
                    }
                }
            }
        }
    }
}

// ---------------------------------------------------- finalize: combine + where
__global__ void finalize_kernel(const float* __restrict__ X, float* __restrict__ out) {
    const int i = blockIdx.x * blockDim.x + threadIdx.x;
    if (i >= NT * DM / 4) return;
    const int t = i / (DM / 4);
    const int d4 = i % (DM / 4);
    const int p0 = g_pairpos[2 * t];
    const int p1 = g_pairpos[2 * t + 1];
    const float4 y0 = *reinterpret_cast<const float4*>(g_Y + (size_t)p0 * DM + d4 * 4);
    const float4 y1 = *reinterpret_cast<const float4*>(g_Y + (size_t)p1 * DM + d4 * 4);
    const float4 xv = reinterpret_cast<const float4*>(X)[i];
    float4 s, o;
    s.x = y0.x + y1.x; s.y = y0.y + y1.y; s.z = y0.z + y1.z; s.w = y0.w + y1.w;
    o.x = (s.x != 0.f) ? s.x : xv.x;
    o.y = (s.y != 0.f) ? s.y : xv.y;
    o.z = (s.z != 0.f) ? s.z : xv.z;
    o.w = (s.w != 0.f) ? s.w : xv.w;
    reinterpret_cast<float4*>(out)[i] = o;
}

extern "C" void kernel_launch(void* const* d_in, const int* in_sizes, int n_in,
                              void* d_out, int out_size) {
    const float* hs   = (const float*)d_in[0];   // [4096, 512]
    const float* prob = (const float*)d_in[1];   // [4096, 2]
    const float* wi   = (const float*)d_in[2];   // [8, 512, 2048]
    const float* wo   = (const float*)d_in[3];   // [8, 2048, 512]
    const int*   eidx = (const int*)d_in[4];     // [4096, 2]
    float* out = (float*)d_out;

    const int SMEM = NSTAGE * STAGE_BYTES + 1024;   // 197632 B
    cudaFuncSetAttribute(gemm_mma<0>, cudaFuncAttributeMaxDynamicSharedMemorySize, SMEM);
    cudaFuncSetAttribute(gemm_mma<1>, cudaFuncAttributeMaxDynamicSharedMemorySize, SMEM);

    route_kernel<<<1, 256>>>(eidx, prob);
    split_x_kernel<<<(NPPAD * (DM / 4) + 255) / 256, 256>>>(hs);
    transpose_split_kernel<<<dim3(DF / 64, DM / 64, NE), 256>>>(wi, DM, DF, 0);
    transpose_split_kernel<<<dim3(DM / 64, DF / 64, NE), 256>>>(wo, DF, DM, 1);

    gemm_mma<0><<<dim3(DF / 128, RBLK, NE), 256, SMEM>>>();
    gemm_mma<1><<<dim3(DM / 128, RBLK, NE), 256, SMEM>>>();

    finalize_kernel<<<(NT * DM / 4 + 255) / 256, 256>>>(hs, out);
}

// round 15
// speedup vs baseline: 1.1640x; 1.1619x over previous
#include <cuda_runtime.h>
#include <cuda_fp16.h>
#include <cstdint>

// Problem constants
#define NT 4096        // B*S tokens
#define DM 512         // d_model
#define DF 2048        // d_ff
#define NE 8           // experts
#define NP 8192        // token-expert pairs
#define NPPAD 10240    // NP + NE*256 padding (expert segments 256-aligned)
#define RBLK  (NPPAD / 256)   // 40 row blocks

// Tile blocks (pre-swizzled, contiguous for cp.async.bulk)
#define ABLK 32768     // 256 rows x 128B (one A tile-chunk)
#define BBLK 16384     // 128 rows x 128B (one B-limb tile-chunk)
#define TILE_A      32768
#define NSTAGE 3
#define WSCALE 64.0f
#define INV_WSCALE (1.0f / 64.0f)

// ---------------------------------------------------------------- scratch
__device__ int   g_count[NE];
__device__ int   g_off[NE];
__device__ int   g_fill[NE];
__device__ int   g_tok[NPPAD];
__device__ float g_coef[NPPAD];
__device__ int   g_pairpos[NP];

// Weights, tiled: [e][nblk][chunk][16384B swizzled block]
__device__ __align__(128) unsigned char g_wiT_hi[(size_t)NE * 16 * 8 * BBLK];
__device__ __align__(128) unsigned char g_wiT_lo[(size_t)NE * 16 * 8 * BBLK];
__device__ __align__(128) unsigned char g_woT_hi[(size_t)NE * 4 * 32 * BBLK];  // single limb
// Activations, tiled: [rowblk][chunk][32768B swizzled block]
__device__ __align__(128) unsigned char g_Xg[(size_t)RBLK * 8 * ABLK];
__device__ __align__(128) unsigned char g_H[(size_t)RBLK * 32 * ABLK];
__device__ __align__(128) float g_Y[(size_t)NPPAD * DM];

// ---------------------------------------------------------------- helpers
__device__ __forceinline__ uint32_t smem_u32(const void* p) {
    uint32_t a;
    asm("{ .reg .u64 t; cvta.to.shared.u64 t, %1; cvt.u32.u64 %0, t; }" : "=r"(a) : "l"(p));
    return a;
}
#define LDSM4(R0, R1, R2, R3, ADDR)                                                \
    asm volatile("ldmatrix.sync.aligned.m8n8.x4.shared.b16 {%0,%1,%2,%3}, [%4];"   \
        : "=r"(R0), "=r"(R1), "=r"(R2), "=r"(R3) : "r"(ADDR))

__device__ __forceinline__ void mma16816(float* c, const uint32_t* a, const uint32_t* b) {
    asm volatile(
        "mma.sync.aligned.m16n8k16.row.col.f32.f16.f16.f32 "
        "{%0,%1,%2,%3}, {%4,%5,%6,%7}, {%8,%9}, {%0,%1,%2,%3};"
        : "+f"(c[0]), "+f"(c[1]), "+f"(c[2]), "+f"(c[3])
        : "r"(a[0]), "r"(a[1]), "r"(a[2]), "r"(a[3]), "r"(b[0]), "r"(b[1]));
}

#define SWZ(x) ((x) ^ (((x) >> 3) & 0x70))

#define MBAR_INIT(a, c) asm volatile("mbarrier.init.shared.b64 [%0], %1;" :: "r"(a), "r"((uint32_t)(c)) : "memory")
#define MBAR_EXPECT_TX(a, b) asm volatile("mbarrier.arrive.expect_tx.shared.b64 _, [%0], %1;" :: "r"(a), "r"((uint32_t)(b)) : "memory")
#define MBAR_WAIT(mbar, parity) do {                                              \
    uint32_t _m = (mbar), _p = (parity), _d;                                      \
    asm volatile("{ .reg .pred p; mbarrier.try_wait.parity.acquire.cta.shared::cta.b64 p, [%1], %2; selp.b32 %0, 1, 0, p; }" \
        : "=r"(_d) : "r"(_m), "r"(_p) : "memory");                                \
    if (!_d) {                                                                    \
        asm volatile("{ .reg .pred P1; WL_%=: mbarrier.try_wait.parity.acquire.cta.shared::cta.b64 P1, [%0], %1, 0x989680; @P1 bra.uni WD_%=; bra.uni WL_%=; WD_%=: }" \
            :: "r"(_m), "r"(_p) : "memory");                                      \
    }                                                                             \
} while (0)
#define BULK_G2S(dst, src, bytes, mbar)                                           \
    asm volatile("cp.async.bulk.shared::cluster.global.mbarrier::complete_tx::bytes [%0], [%1], %2, [%3];" \
        :: "r"(dst), "l"(src), "r"((uint32_t)(bytes)), "r"(mbar) : "memory")

__device__ __forceinline__ uint32_t pack2h(__half a, __half b) {
    __half2 t = __halves2half2(a, b);
    return *reinterpret_cast<uint32_t*>(&t);
}
__device__ __forceinline__ void split1h(float v, __half& h, __half& l) {
    h = __float2half(v);
    l = __float2half(v - __half2float(h));
}

// ---------------------------------------------------------------- routing
__global__ void route_kernel(const int* __restrict__ eidx, const float* __restrict__ prob) {
    __shared__ int s_cnt[NE];
    const int tid = threadIdx.x;
    if (tid < NE) s_cnt[tid] = 0;
    __syncthreads();
    for (int p = tid; p < NP; p += blockDim.x) atomicAdd(&s_cnt[eidx[p]], 1);
    __syncthreads();
    if (tid == 0) {
        int start = 0;
        for (int e = 0; e < NE; e++) {
            g_count[e] = s_cnt[e]; g_off[e] = start; g_fill[e] = start;
            start += (s_cnt[e] + 255) & ~255;   // 256-aligned segments
        }
    }
    for (int i = tid; i < NPPAD; i += blockDim.x) { g_tok[i] = 0; g_coef[i] = 0.f; }
    __syncthreads();
    for (int p = tid; p < NP; p += blockDim.x) {
        const int e = eidx[p];
        const int pos = atomicAdd(&g_fill[e], 1);
        const float df = (p & 1) ? 0.25f : 0.5f;
        g_pairpos[p] = pos;
        g_tok[pos]   = p >> 1;
        g_coef[pos]  = df * prob[p];
    }
}

// ------------------------- gather activations -> fp16, tiled+swizzled blocks
__global__ void split_x_kernel(const float* __restrict__ X) {
    const int i = blockIdx.x * 256 + threadIdx.x;       // over NPPAD * (DM/4)
    if (i >= NPPAD * (DM / 4)) return;
    const int row = i / (DM / 4);
    const int c4  = i % (DM / 4);                       // 16B unit in source row
    const float4 v = reinterpret_cast<const float4*>(X + (size_t)g_tok[row] * DM)[c4];
    const uint2 o = make_uint2(pack2h(__float2half(v.x), __float2half(v.y)),
                               pack2h(__float2half(v.z), __float2half(v.w)));
    const int blk = row >> 8, rowin = row & 255;
    const int ch  = c4 >> 4;                            // 64-col chunk
    const uint32_t byte = SWZ((uint32_t)(rowin * 128 + (c4 & 15) * 8));
    *reinterpret_cast<uint2*>(g_Xg + ((size_t)blk * 8 + ch) * ABLK + byte) = o;
}

// --------- transpose + scale(x64) + split weights -> tiled+swizzled limb blocks
// src [e][R][C] fp32 -> limbs [e][n/128][k/64][SWZ((n%128)*128 + (k%64)*2)]
// which=0 (wi): hi+lo limbs.  which=1 (wo): hi limb only.
__global__ void transpose_split_kernel(const float* __restrict__ src, int R, int C, int which) {
    unsigned char* dhi = which ? g_woT_hi : g_wiT_hi;
    const int e = blockIdx.z;
    const int NBLKn = C / 128, NCHk = R / 64;
    const float* s = src + (size_t)e * R * C;

    __shared__ float t[64][65];
    const int c0 = blockIdx.x * 64, r0 = blockIdx.y * 64;
    const int tid = threadIdx.x;

    const int lr = tid >> 4;          // 0..15
    const int lc = (tid & 15) * 4;    // 0..60
#pragma unroll
    for (int it = 0; it < 4; it++) {
        const int r = it * 16 + lr;
        const float4 v = *reinterpret_cast<const float4*>(s + (size_t)(r0 + r) * C + c0 + lc);
        t[lc + 0][r] = v.x; t[lc + 1][r] = v.y; t[lc + 2][r] = v.z; t[lc + 3][r] = v.w;
    }
    __syncthreads();

    const int oc = tid >> 2;          // 0..63  (output n within 64-tile)
    const int rs = (tid & 3) * 16;    // k start 0,16,32,48
    uint32_t hw[8], lw[8];
#pragma unroll
    for (int q = 0; q < 8; q++) {
        const float v0 = t[oc][rs + 2 * q]     * WSCALE;
        const float v1 = t[oc][rs + 2 * q + 1] * WSCALE;
        __half h0, l0, h1, l1;
        split1h(v0, h0, l0); split1h(v1, h1, l1);
        hw[q] = pack2h(h0, h1); lw[q] = pack2h(l0, l1);
    }
    const int n = c0 + oc, k = r0 + rs;
    const size_t boff = (((size_t)e * NBLKn + (n >> 7)) * NCHk + (k >> 6)) * BBLK;
    const int nin = n & 127, kin = k & 63;
    const uint32_t b0 = SWZ((uint32_t)(nin * 128 + kin * 2));
    const uint32_t b1 = SWZ((uint32_t)(nin * 128 + kin * 2 + 16));
    *reinterpret_cast<uint4*>(dhi + boff + b0) = make_uint4(hw[0], hw[1], hw[2], hw[3]);
    *reinterpret_cast<uint4*>(dhi + boff + b1) = make_uint4(hw[4], hw[5], hw[6], hw[7]);
    if (which == 0) {
        *reinterpret_cast<uint4*>(g_wiT_lo + boff + b0) = make_uint4(lw[0], lw[1], lw[2], lw[3]);
        *reinterpret_cast<uint4*>(g_wiT_lo + boff + b1) = make_uint4(lw[4], lw[5], lw[6], lw[7]);
    }
}

// ------------------------------------------------- HMMA GEMM (both layers)
// MODE 0: H = relu(Xg @ wiT'^T)/64      [K=DM, N=DF] -> fp16 tiled blocks; W hi+lo
// MODE 1: Y = (coef/64) * (H @ woT'^T)  [K=DF, N=DM] -> fp32; W hi only
// CTA: 256 M x 128 N, 8 warps 4(M)x2(N), warp 64x64.
// Loads: cp.async.bulk of pre-swizzled blocks, mbarrier-paced, 3 stages.
template <int MODE>
__global__ __launch_bounds__(256)
void gemm_mma() {
    constexpr int NC    = (MODE == 0) ? (DM / 64) : (DF / 64);
    constexpr int LIMBS = (MODE == 0) ? 2 : 1;
    constexpr int STAGE = TILE_A + LIMBS * BBLK;   // 64KB or 48KB

    const int e = blockIdx.z;
    const int cnt = g_count[e];
    const int mbase = blockIdx.y * 256;
    if (mbase >= cnt) return;
    const int off = g_off[e];
    const int nbase = blockIdx.x * 128;
    const int tid = threadIdx.x;
    const int lid = tid & 31;
    const int wid = tid >> 5;
    const int wm = wid >> 1;      // 0..3 -> 64-row slab
    const int wn = wid & 1;       // 0..1 -> 64-col slab

    extern __shared__ char dynsmem[];
    const uint32_t raw  = smem_u32(dynsmem);
    const uint32_t base = (raw + 1023) & ~1023u;
    __shared__ __align__(8) uint64_t s_mbar[NSTAGE];
    uint32_t mb[NSTAGE];
#pragma unroll
    for (int s = 0; s < NSTAGE; s++) mb[s] = smem_u32(&s_mbar[s]);

    if (tid == 0) {
#pragma unroll
        for (int s = 0; s < NSTAGE; s++) MBAR_INIT(mb[s], 1);
    }
    __syncthreads();

    const int ablk = (off + mbase) >> 8;
    const unsigned char* Asrc = (MODE == 0)
        ? (g_Xg + (size_t)ablk * 8  * ABLK)
        : (g_H  + (size_t)ablk * 32 * ABLK);
    const unsigned char* Bhi = (MODE == 0)
        ? (g_wiT_hi + (((size_t)e * 16 + (nbase >> 7)) * 8)  * BBLK)
        : (g_woT_hi + (((size_t)e * 4  + (nbase >> 7)) * 32) * BBLK);
    const unsigned char* Blo = (MODE == 0)
        ? (g_wiT_lo + (((size_t)e * 16 + (nbase >> 7)) * 8)  * BBLK)
        : nullptr;

    auto issue = [&](int c) {
        const int st = c % NSTAGE;
        const uint32_t m = mb[st];
        const uint32_t tb = base + st * STAGE;
        MBAR_EXPECT_TX(m, STAGE);
        BULK_G2S(tb,          Asrc + (size_t)c * ABLK, ABLK, m);
        BULK_G2S(tb + TILE_A, Bhi  + (size_t)c * BBLK, BBLK, m);
        if (LIMBS == 2)
            BULK_G2S(tb + TILE_A + BBLK, Blo + (size_t)c * BBLK, BBLK, m);
    };

    float acc[4][8][4];
#pragma unroll
    for (int f = 0; f < 4; f++)
#pragma unroll
        for (int j = 0; j < 8; j++)
#pragma unroll
            for (int q = 0; q < 4; q++) acc[f][j][q] = 0.f;

    const int bq  = (lid & 7) | ((lid >> 4) << 3);   // B: n row within 16-group
    const int bkh = ((lid >> 3) & 1) * 16;           // B: k-half byte offset
    const int ar  = lid & 15;                        // A: m row within 16-group
    const int akh = (lid >> 4) * 16;                 // A: k-half byte offset

    if (tid == 0) { issue(0); issue(1); issue(2); }  // NC >= 8 always

    for (int c = 0; c < NC; c++) {
        const int st = c % NSTAGE;
        MBAR_WAIT(mb[st], (c / NSTAGE) & 1);

        const uint32_t tb   = base + st * STAGE;
        const uint32_t pA   = tb;
        const uint32_t pBhi = tb + TILE_A;
        const uint32_t pBlo = tb + TILE_A + BBLK;

#pragma unroll
        for (int s = 0; s < 4; s++) {
            const int kb = s * 32;                   // byte offset of k16 step
            uint32_t bh[8][2], bl[8][2];
#pragma unroll
            for (int P = 0; P < 4; P++) {            // 64 n-cols = 4 x 16 rows
                const uint32_t a = SWZ((wn * 64 + P * 16 + bq) * 128 + kb + bkh);
                LDSM4(bh[2 * P][0], bh[2 * P][1], bh[2 * P + 1][0], bh[2 * P + 1][1], pBhi + a);
                if (LIMBS == 2)
                    LDSM4(bl[2 * P][0], bl[2 * P][1], bl[2 * P + 1][0], bl[2 * P + 1][1], pBlo + a);
            }
#pragma unroll
            for (int f = 0; f < 4; f++) {
                uint32_t av[4];
                const uint32_t a = SWZ((wm * 64 + f * 16 + ar) * 128 + kb + akh);
                LDSM4(av[0], av[1], av[2], av[3], pA + a);
#pragma unroll
                for (int j = 0; j < 8; j++) mma16816(acc[f][j], av, bh[j]);
                if (LIMBS == 2) {
#pragma unroll
                    for (int j = 0; j < 8; j++) mma16816(acc[f][j], av, bl[j]);
                }
            }
        }
        __syncthreads();                      // all warps done with stage st
        if (tid == 0 && c + NSTAGE < NC) issue(c + NSTAGE);
    }

    // ------------------------------------------------------------ epilogue
#pragma unroll
    for (int f = 0; f < 4; f++) {
        const int rib0 = wm * 64 + f * 16 + (lid >> 2);      // row in 256-block
#pragma unroll
        for (int h = 0; h < 2; h++) {
            const int rib = rib0 + h * 8;
            const int r = mbase + rib;
            if (r < cnt) {
                if (MODE == 0) {
                    // H tiled: [ablk][col/64][SWZ(rib*128 + (col%64)*2)]
                    const int ch = (nbase >> 6) + wn;
                    unsigned char* Hb = g_H + ((size_t)ablk * 32 + ch) * ABLK;
#pragma unroll
                    for (int j = 0; j < 8; j++) {
                        const float v0 = fmaxf(acc[f][j][2 * h], 0.f) * INV_WSCALE;
                        const float v1 = fmaxf(acc[f][j][2 * h + 1], 0.f) * INV_WSCALE;
                        const uint32_t byte = SWZ((uint32_t)(rib * 128 + (lid & 3) * 4 + j * 16));
                        *reinterpret_cast<uint32_t*>(Hb + byte) = pack2h(__float2half(v0), __float2half(v1));
                    }
                } else {
                    const float cf = g_coef[off + r] * INV_WSCALE;
                    const int colb = nbase + wn * 64 + (lid & 3) * 2;
                    float* Yp = g_Y + (size_t)(off + r) * DM + colb;
#pragma unroll
                    for (int j = 0; j < 8; j++) {
                        float2 v;
                        v.x = cf * acc[f][j][2 * h];
                        v.y = cf * acc[f][j][2 * h + 1];
                        *reinterpret_cast<float2*>(Yp + j * 8) = v;
                    }
                }
            }
        }
    }
}

// ---------------------------------------------------- finalize: combine + where
__global__ void finalize_kernel(const float* __restrict__ X, float* __restrict__ out) {
    const int i = blockIdx.x * blockDim.x + threadIdx.x;
    if (i >= NT * DM / 4) return;
    const int t = i / (DM / 4);
    const int d4 = i % (DM / 4);
    const int p0 = g_pairpos[2 * t];
    const int p1 = g_pairpos[2 * t + 1];
    const float4 y0 = *reinterpret_cast<const float4*>(g_Y + (size_t)p0 * DM + d4 * 4);
    const float4 y1 = *reinterpret_cast<const float4*>(g_Y + (size_t)p1 * DM + d4 * 4);
    const float4 xv = reinterpret_cast<const float4*>(X)[i];
    float4 s, o;
    s.x = y0.x + y1.x; s.y = y0.y + y1.y; s.z = y0.z + y1.z; s.w = y0.w + y1.w;
    o.x = (s.x != 0.f) ? s.x : xv.x;
    o.y = (s.y != 0.f) ? s.y : xv.y;
    o.z = (s.z != 0.f) ? s.z : xv.z;
    o.w = (s.w != 0.f) ? s.w : xv.w;
    reinterpret_cast<float4*>(out)[i] = o;
}

extern "C" void kernel_launch(void* const* d_in, const int* in_sizes, int n_in,
                              void* d_out, int out_size) {
    const float* hs   = (const float*)d_in[0];   // [4096, 512]
    const float* prob = (const float*)d_in[1];   // [4096, 2]
    const float* wi   = (const float*)d_in[2];   // [8, 512, 2048]
    const float* wo   = (const float*)d_in[3];   // [8, 2048, 512]
    const int*   eidx = (const int*)d_in[4];     // [4096, 2]
    float* out = (float*)d_out;

    const int SMEM0 = NSTAGE * (TILE_A + 2 * BBLK) + 1024;  // 197632
    const int SMEM1 = NSTAGE * (TILE_A + 1 * BBLK) + 1024;  // 148480
    cudaFuncSetAttribute(gemm_mma<0>, cudaFuncAttributeMaxDynamicSharedMemorySize, SMEM0);
    cudaFuncSetAttribute(gemm_mma<1>, cudaFuncAttributeMaxDynamicSharedMemorySize, SMEM1);

    route_kernel<<<1, 256>>>(eidx, prob);
    split_x_kernel<<<(NPPAD * (DM / 4) + 255) / 256, 256>>>(hs);
    transpose_split_kernel<<<dim3(DF / 64, DM / 64, NE), 256>>>(wi, DM, DF, 0);
    transpose_split_kernel<<<dim3(DM / 64, DF / 64, NE), 256>>>(wo, DF, DM, 1);

    gemm_mma<0><<<dim3(DF / 128, RBLK, NE), 256, SMEM0>>>();
    gemm_mma<1><<<dim3(DM / 128, RBLK, NE), 256, SMEM1>>>();

    finalize_kernel<<<(NT * DM / 4 + 255) / 256, 256>>>(hs, out);
}

// round 16
// speedup vs baseline: 1.4066x; 1.2085x over previous
#include <cuda_runtime.h>
#include <cuda_fp16.h>
#include <cstdint>

// Problem constants
#define NT 4096        // B*S tokens
#define DM 512         // d_model
#define DF 2048        // d_ff
#define NE 8           // experts
#define NP 8192        // token-expert pairs
#define NPPAD 10240    // NP + NE*256 padding (expert segments 256-aligned)
#define RBLK  (NPPAD / 256)   // 40 row blocks

// Tile blocks (pre-swizzled, contiguous for cp.async.bulk)
#define ABLK 32768     // 256 rows x 128B (one A tile-chunk)
#define BBLK 16384     // 128 rows x 128B (one B tile-chunk)
#define TILE_A      32768
#define STAGE_BYTES (TILE_A + BBLK)   // 48 KB
#define NSTAGE 3
#define WSCALE 64.0f
#define INV_WSCALE (1.0f / 64.0f)

// ---------------------------------------------------------------- scratch
__device__ int   g_count[NE];
__device__ int   g_off[NE];
__device__ int   g_fill[NE];
__device__ int   g_tok[NPPAD];
__device__ float g_coef[NPPAD];
__device__ int   g_pairpos[NP];

// Weights, tiled: [e][nblk][chunk][16384B swizzled block], single fp16 limb (x64)
__device__ __align__(128) unsigned char g_wiT[(size_t)NE * 16 * 8 * BBLK];
__device__ __align__(128) unsigned char g_woT[(size_t)NE * 4 * 32 * BBLK];
// Activations, tiled: [rowblk][chunk][32768B swizzled block]
__device__ __align__(128) unsigned char g_Xg[(size_t)RBLK * 8 * ABLK];
__device__ __align__(128) unsigned char g_H[(size_t)RBLK * 32 * ABLK];
__device__ __align__(128) float g_Y[(size_t)NPPAD * DM];

// ---------------------------------------------------------------- helpers
__device__ __forceinline__ uint32_t smem_u32(const void* p) {
    uint32_t a;
    asm("{ .reg .u64 t; cvta.to.shared.u64 t, %1; cvt.u32.u64 %0, t; }" : "=r"(a) : "l"(p));
    return a;
}
#define LDSM4(R0, R1, R2, R3, ADDR)                                                \
    asm volatile("ldmatrix.sync.aligned.m8n8.x4.shared.b16 {%0,%1,%2,%3}, [%4];"   \
        : "=r"(R0), "=r"(R1), "=r"(R2), "=r"(R3) : "r"(ADDR))

__device__ __forceinline__ void mma16816(float* c, const uint32_t* a, const uint32_t* b) {
    asm volatile(
        "mma.sync.aligned.m16n8k16.row.col.f32.f16.f16.f32 "
        "{%0,%1,%2,%3}, {%4,%5,%6,%7}, {%8,%9}, {%0,%1,%2,%3};"
        : "+f"(c[0]), "+f"(c[1]), "+f"(c[2]), "+f"(c[3])
        : "r"(a[0]), "r"(a[1]), "r"(a[2]), "r"(a[3]), "r"(b[0]), "r"(b[1]));
}

#define SWZ(x) ((x) ^ (((x) >> 3) & 0x70))

#define MBAR_INIT(a, c) asm volatile("mbarrier.init.shared.b64 [%0], %1;" :: "r"(a), "r"((uint32_t)(c)) : "memory")
#define MBAR_EXPECT_TX(a, b) asm volatile("mbarrier.arrive.expect_tx.shared.b64 _, [%0], %1;" :: "r"(a), "r"((uint32_t)(b)) : "memory")
#define MBAR_WAIT(mbar, parity) do {                                              \
    uint32_t _m = (mbar), _p = (parity), _d;                                      \
    asm volatile("{ .reg .pred p; mbarrier.try_wait.parity.acquire.cta.shared::cta.b64 p, [%1], %2; selp.b32 %0, 1, 0, p; }" \
        : "=r"(_d) : "r"(_m), "r"(_p) : "memory");                                \
    if (!_d) {                                                                    \
        asm volatile("{ .reg .pred P1; WL_%=: mbarrier.try_wait.parity.acquire.cta.shared::cta.b64 P1, [%0], %1, 0x989680; @P1 bra.uni WD_%=; bra.uni WL_%=; WD_%=: }" \
            :: "r"(_m), "r"(_p) : "memory");                                      \
    }                                                                             \
} while (0)
#define BULK_G2S(dst, src, bytes, mbar)                                           \
    asm volatile("cp.async.bulk.shared::cluster.global.mbarrier::complete_tx::bytes [%0], [%1], %2, [%3];" \
        :: "r"(dst), "l"(src), "r"((uint32_t)(bytes)), "r"(mbar) : "memory")

__device__ __forceinline__ uint32_t pack2h(__half a, __half b) {
    __half2 t = __halves2half2(a, b);
    return *reinterpret_cast<uint32_t*>(&t);
}

// ---------------------------------------------------------------- routing
__global__ void route_kernel(const int* __restrict__ eidx, const float* __restrict__ prob) {
    __shared__ int s_cnt[NE];
    const int tid = threadIdx.x;
    if (tid < NE) s_cnt[tid] = 0;
    __syncthreads();
    for (int p = tid; p < NP; p += blockDim.x) atomicAdd(&s_cnt[eidx[p]], 1);
    __syncthreads();
    if (tid == 0) {
        int start = 0;
        for (int e = 0; e < NE; e++) {
            g_count[e] = s_cnt[e]; g_off[e] = start; g_fill[e] = start;
            start += (s_cnt[e] + 255) & ~255;   // 256-aligned segments
        }
    }
    for (int i = tid; i < NPPAD; i += blockDim.x) { g_tok[i] = 0; g_coef[i] = 0.f; }
    __syncthreads();
    for (int p = tid; p < NP; p += blockDim.x) {
        const int e = eidx[p];
        const int pos = atomicAdd(&g_fill[e], 1);
        const float df = (p & 1) ? 0.25f : 0.5f;
        g_pairpos[p] = pos;
        g_tok[pos]   = p >> 1;
        g_coef[pos]  = df * prob[p];
    }
}

// ------------------------- gather activations -> fp16, tiled+swizzled blocks
__global__ void split_x_kernel(const float* __restrict__ X) {
    const int i = blockIdx.x * 256 + threadIdx.x;       // over NPPAD * (DM/4)
    if (i >= NPPAD * (DM / 4)) return;
    const int row = i / (DM / 4);
    const int c4  = i % (DM / 4);                       // 16B unit in source row
    const float4 v = reinterpret_cast<const float4*>(X + (size_t)g_tok[row] * DM)[c4];
    const uint2 o = make_uint2(pack2h(__float2half(v.x), __float2half(v.y)),
                               pack2h(__float2half(v.z), __float2half(v.w)));
    const int blk = row >> 8, rowin = row & 255;
    const int ch  = c4 >> 4;                            // 64-col chunk
    const uint32_t byte = SWZ((uint32_t)(rowin * 128 + (c4 & 15) * 8));
    *reinterpret_cast<uint2*>(g_Xg + ((size_t)blk * 8 + ch) * ABLK + byte) = o;
}

// --------- transpose + scale(x64) weights -> tiled+swizzled blocks (fp16)
// src [e][R][C] fp32 -> [e][n/128][k/64][SWZ((n%128)*128 + (k%64)*2)]
__global__ void transpose_split_kernel(const float* __restrict__ src, int R, int C, int which) {
    unsigned char* dst = which ? g_woT : g_wiT;
    const int e = blockIdx.z;
    const int NBLKn = C / 128, NCHk = R / 64;
    const float* s = src + (size_t)e * R * C;

    __shared__ float t[64][65];
    const int c0 = blockIdx.x * 64, r0 = blockIdx.y * 64;
    const int tid = threadIdx.x;

    const int lr = tid >> 4;          // 0..15
    const int lc = (tid & 15) * 4;    // 0..60
#pragma unroll
    for (int it = 0; it < 4; it++) {
        const int r = it * 16 + lr;
        const float4 v = *reinterpret_cast<const float4*>(s + (size_t)(r0 + r) * C + c0 + lc);
        t[lc + 0][r] = v.x; t[lc + 1][r] = v.y; t[lc + 2][r] = v.z; t[lc + 3][r] = v.w;
    }
    __syncthreads();

    const int oc = tid >> 2;          // 0..63  (output n within 64-tile)
    const int rs = (tid & 3) * 16;    // k start 0,16,32,48
    uint32_t hw[8];
#pragma unroll
    for (int q = 0; q < 8; q++) {
        const float v0 = t[oc][rs + 2 * q]     * WSCALE;
        const float v1 = t[oc][rs + 2 * q + 1] * WSCALE;
        hw[q] = pack2h(__float2half(v0), __float2half(v1));
    }
    const int n = c0 + oc, k = r0 + rs;
    const size_t boff = (((size_t)e * NBLKn + (n >> 7)) * NCHk + (k >> 6)) * BBLK;
    const int nin = n & 127, kin = k & 63;
    const uint32_t b0 = SWZ((uint32_t)(nin * 128 + kin * 2));
    const uint32_t b1 = SWZ((uint32_t)(nin * 128 + kin * 2 + 16));
    *reinterpret_cast<uint4*>(dst + boff + b0) = make_uint4(hw[0], hw[1], hw[2], hw[3]);
    *reinterpret_cast<uint4*>(dst + boff + b1) = make_uint4(hw[4], hw[5], hw[6], hw[7]);
}

// ------------------------------------------------- HMMA GEMM (both layers)
// MODE 0: H = relu(Xg @ wiT'^T)/64      [K=DM, N=DF] -> fp16 tiled blocks
// MODE 1: Y = (coef/64) * (H @ woT'^T)  [K=DF, N=DM] -> fp32
// Single fp16 weight limb. CTA: 256 M x 128 N, 8 warps 4(M)x2(N), warp 64x64.
// Loads: cp.async.bulk of pre-swizzled blocks, mbarrier-paced, 3 stages.
template <int MODE>
__global__ __launch_bounds__(256)
void gemm_mma() {
    constexpr int NC = (MODE == 0) ? (DM / 64) : (DF / 64);

    const int e = blockIdx.z;
    const int cnt = g_count[e];
    const int mbase = blockIdx.y * 256;
    if (mbase >= cnt) return;
    const int off = g_off[e];
    const int nbase = blockIdx.x * 128;
    const int tid = threadIdx.x;
    const int lid = tid & 31;
    const int wid = tid >> 5;
    const int wm = wid >> 1;      // 0..3 -> 64-row slab
    const int wn = wid & 1;       // 0..1 -> 64-col slab

    extern __shared__ char dynsmem[];
    const uint32_t raw  = smem_u32(dynsmem);
    const uint32_t base = (raw + 1023) & ~1023u;
    __shared__ __align__(8) uint64_t s_mbar[NSTAGE];
    uint32_t mb[NSTAGE];
#pragma unroll
    for (int s = 0; s < NSTAGE; s++) mb[s] = smem_u32(&s_mbar[s]);

    if (tid == 0) {
#pragma unroll
        for (int s = 0; s < NSTAGE; s++) MBAR_INIT(mb[s], 1);
    }
    __syncthreads();

    const int ablk = (off + mbase) >> 8;
    const unsigned char* Asrc = (MODE == 0)
        ? (g_Xg + (size_t)ablk * 8  * ABLK)
        : (g_H  + (size_t)ablk * 32 * ABLK);
    const unsigned char* Bsrc = (MODE == 0)
        ? (g_wiT + (((size_t)e * 16 + (nbase >> 7)) * 8)  * BBLK)
        : (g_woT + (((size_t)e * 4  + (nbase >> 7)) * 32) * BBLK);

    auto issue = [&](int c) {
        const int st = c % NSTAGE;
        const uint32_t m = mb[st];
        const uint32_t tb = base + st * STAGE_BYTES;
        MBAR_EXPECT_TX(m, STAGE_BYTES);
        BULK_G2S(tb,          Asrc + (size_t)c * ABLK, ABLK, m);
        BULK_G2S(tb + TILE_A, Bsrc + (size_t)c * BBLK, BBLK, m);
    };

    float acc[4][8][4];
#pragma unroll
    for (int f = 0; f < 4; f++)
#pragma unroll
        for (int j = 0; j < 8; j++)
#pragma unroll
            for (int q = 0; q < 4; q++) acc[f][j][q] = 0.f;

    const int bq  = (lid & 7) | ((lid >> 4) << 3);   // B: n row within 16-group
    const int bkh = ((lid >> 3) & 1) * 16;           // B: k-half byte offset
    const int ar  = lid & 15;                        // A: m row within 16-group
    const int akh = (lid >> 4) * 16;                 // A: k-half byte offset

    if (tid == 0) { issue(0); issue(1); issue(2); }  // NC >= 8 always

    for (int c = 0; c < NC; c++) {
        const int st = c % NSTAGE;
        MBAR_WAIT(mb[st], (c / NSTAGE) & 1);

        const uint32_t tb = base + st * STAGE_BYTES;
        const uint32_t pA = tb;
        const uint32_t pB = tb + TILE_A;

#pragma unroll
        for (int s = 0; s < 4; s++) {
            const int kb = s * 32;                   // byte offset of k16 step
            uint32_t bh[8][2];
#pragma unroll
            for (int P = 0; P < 4; P++) {            // 64 n-cols = 4 x 16 rows
                const uint32_t a = SWZ((wn * 64 + P * 16 + bq) * 128 + kb + bkh);
                LDSM4(bh[2 * P][0], bh[2 * P][1], bh[2 * P + 1][0], bh[2 * P + 1][1], pB + a);
            }
#pragma unroll
            for (int f = 0; f < 4; f++) {
                uint32_t av[4];
                const uint32_t a = SWZ((wm * 64 + f * 16 + ar) * 128 + kb + akh);
                LDSM4(av[0], av[1], av[2], av[3], pA + a);
#pragma unroll
                for (int j = 0; j < 8; j++) mma16816(acc[f][j], av, bh[j]);
            }
        }
        __syncthreads();                      // all warps done with stage st
        if (tid == 0 && c + NSTAGE < NC) issue(c + NSTAGE);
    }

    // ------------------------------------------------------------ epilogue
#pragma unroll
    for (int f = 0; f < 4; f++) {
        const int rib0 = wm * 64 + f * 16 + (lid >> 2);      // row in 256-block
#pragma unroll
        for (int h = 0; h < 2; h++) {
            const int rib = rib0 + h * 8;
            const int r = mbase + rib;
            if (r < cnt) {
                if (MODE == 0) {
                    // H tiled: [ablk][col/64][SWZ(rib*128 + (col%64)*2)]
                    const int ch = (nbase >> 6) + wn;
                    unsigned char* Hb = g_H + ((size_t)ablk * 32 + ch) * ABLK;
#pragma unroll
                    for (int j = 0; j < 8; j++) {
                        const float v0 = fmaxf(acc[f][j][2 * h], 0.f) * INV_WSCALE;
                        const float v1 = fmaxf(acc[f][j][2 * h + 1], 0.f) * INV_WSCALE;
                        const uint32_t byte = SWZ((uint32_t)(rib * 128 + (lid & 3) * 4 + j * 16));
                        *reinterpret_cast<uint32_t*>(Hb + byte) = pack2h(__float2half(v0), __float2half(v1));
                    }
                } else {
                    const float cf = g_coef[off + r] * INV_WSCALE;
                    const int colb = nbase + wn * 64 + (lid & 3) * 2;
                    float* Yp = g_Y + (size_t)(off + r) * DM + colb;
#pragma unroll
                    for (int j = 0; j < 8; j++) {
                        float2 v;
                        v.x = cf * acc[f][j][2 * h];
                        v.y = cf * acc[f][j][2 * h + 1];
                        *reinterpret_cast<float2*>(Yp + j * 8) = v;
                    }
                }
            }
        }
    }
}

// ---------------------------------------------------- finalize: combine + where
__global__ void finalize_kernel(const float* __restrict__ X, float* __restrict__ out) {
    const int i = blockIdx.x * blockDim.x + threadIdx.x;
    if (i >= NT * DM / 4) return;
    const int t = i / (DM / 4);
    const int d4 = i % (DM / 4);
    const int p0 = g_pairpos[2 * t];
    const int p1 = g_pairpos[2 * t + 1];
    const float4 y0 = *reinterpret_cast<const float4*>(g_Y + (size_t)p0 * DM + d4 * 4);
    const float4 y1 = *reinterpret_cast<const float4*>(g_Y + (size_t)p1 * DM + d4 * 4);
    const float4 xv = reinterpret_cast<const float4*>(X)[i];
    float4 s, o;
    s.x = y0.x + y1.x; s.y = y0.y + y1.y; s.z = y0.z + y1.z; s.w = y0.w + y1.w;
    o.x = (s.x != 0.f) ? s.x : xv.x;
    o.y = (s.y != 0.f) ? s.y : xv.y;
    o.z = (s.z != 0.f) ? s.z : xv.z;
    o.w = (s.w != 0.f) ? s.w : xv.w;
    reinterpret_cast<float4*>(out)[i] = o;
}

extern "C" void kernel_launch(void* const* d_in, const int* in_sizes, int n_in,
                              void* d_out, int out_size) {
    const float* hs   = (const float*)d_in[0];   // [4096, 512]
    const float* prob = (const float*)d_in[1];   // [4096, 2]
    const float* wi   = (const float*)d_in[2];   // [8, 512, 2048]
    const float* wo   = (const float*)d_in[3];   // [8, 2048, 512]
    const int*   eidx = (const int*)d_in[4];     // [4096, 2]
    float* out = (float*)d_out;

    const int SMEM = NSTAGE * STAGE_BYTES + 1024;   // 148480 B
    cudaFuncSetAttribute(gemm_mma<0>, cudaFuncAttributeMaxDynamicSharedMemorySize, SMEM);
    cudaFuncSetAttribute(gemm_mma<1>, cudaFuncAttributeMaxDynamicSharedMemorySize, SMEM);

    route_kernel<<<1, 256>>>(eidx, prob);
    split_x_kernel<<<(NPPAD * (DM / 4) + 255) / 256, 256>>>(hs);
    transpose_split_kernel<<<dim3(DF / 64, DM / 64, NE), 256>>>(wi, DM, DF, 0);
    transpose_split_kernel<<<dim3(DM / 64, DF / 64, NE), 256>>>(wo, DF, DM, 1);

    gemm_mma<0><<<dim3(DF / 128, RBLK, NE), 256, SMEM>>>();
    gemm_mma<1><<<dim3(DM / 128, RBLK, NE), 256, SMEM>>>();

    finalize_kernel<<<(NT * DM / 4 + 255) / 256, 256>>>(hs, out);
}

// round 17
// speedup vs baseline: 1.5337x; 1.0903x over previous
#include <cuda_runtime.h>
#include <cuda_fp16.h>
#include <cstdint>

// Problem constants
#define NT 4096        // B*S tokens
#define DM 512         // d_model
#define DF 2048        // d_ff
#define NE 8           // experts
#define NP 8192        // token-expert pairs
#define NPPAD 10240    // NP + NE*256 padding (expert segments 256-aligned)
#define RBLK  (NPPAD / 256)   // 40 row blocks (256-row storage blocks)

// Tile blocks (pre-swizzled, contiguous for cp.async.bulk)
#define ABLK 32768     // 256 rows x 128B (one A storage block per 64-k chunk)
#define AHALF 16384    // 128-row half block (bulk-copy unit)
#define BBLK 16384     // 128 rows x 128B (one B tile-chunk)
#define STAGE_BYTES (AHALF + BBLK)   // 32 KB
#define NSTAGE 3
#define WSCALE 64.0f
#define INV_WSCALE (1.0f / 64.0f)

// ---------------------------------------------------------------- scratch
__device__ int   g_count[NE];
__device__ int   g_off[NE];
__device__ int   g_fill[NE];
__device__ int   g_tok[NPPAD];
__device__ float g_coef[NPPAD];
__device__ int   g_pairpos[NP];

// Weights, tiled: [e][nblk][chunk][16384B swizzled block], single fp16 limb (x64)
__device__ __align__(128) unsigned char g_wiT[(size_t)NE * 16 * 8 * BBLK];
__device__ __align__(128) unsigned char g_woT[(size_t)NE * 4 * 32 * BBLK];
// Activations, tiled: [rowblk][chunk][32768B swizzled block]
__device__ __align__(128) unsigned char g_Xg[(size_t)RBLK * 8 * ABLK];
__device__ __align__(128) unsigned char g_H[(size_t)RBLK * 32 * ABLK];
__device__ __align__(128) float g_Y[(size_t)NPPAD * DM];

// ---------------------------------------------------------------- helpers
__device__ __forceinline__ uint32_t smem_u32(const void* p) {
    uint32_t a;
    asm("{ .reg .u64 t; cvta.to.shared.u64 t, %1; cvt.u32.u64 %0, t; }" : "=r"(a) : "l"(p));
    return a;
}
#define LDSM4(R0, R1, R2, R3, ADDR)                                                \
    asm volatile("ldmatrix.sync.aligned.m8n8.x4.shared.b16 {%0,%1,%2,%3}, [%4];"   \
        : "=r"(R0), "=r"(R1), "=r"(R2), "=r"(R3) : "r"(ADDR))

__device__ __forceinline__ void mma16816(float* c, const uint32_t* a, const uint32_t* b) {
    asm volatile(
        "mma.sync.aligned.m16n8k16.row.col.f32.f16.f16.f32 "
        "{%0,%1,%2,%3}, {%4,%5,%6,%7}, {%8,%9}, {%0,%1,%2,%3};"
        : "+f"(c[0]), "+f"(c[1]), "+f"(c[2]), "+f"(c[3])
        : "r"(a[0]), "r"(a[1]), "r"(a[2]), "r"(a[3]), "r"(b[0]), "r"(b[1]));
}

#define SWZ(x) ((x) ^ (((x) >> 3) & 0x70))

#define MBAR_INIT(a, c) asm volatile("mbarrier.init.shared.b64 [%0], %1;" :: "r"(a), "r"((uint32_t)(c)) : "memory")
#define MBAR_EXPECT_TX(a, b) asm volatile("mbarrier.arrive.expect_tx.shared.b64 _, [%0], %1;" :: "r"(a), "r"((uint32_t)(b)) : "memory")
#define MBAR_WAIT(mbar, parity) do {                                              \
    uint32_t _m = (mbar), _p = (parity), _d;                                      \
    asm volatile("{ .reg .pred p; mbarrier.try_wait.parity.acquire.cta.shared::cta.b64 p, [%1], %2; selp.b32 %0, 1, 0, p; }" \
        : "=r"(_d) : "r"(_m), "r"(_p) : "memory");                                \
    if (!_d) {                                                                    \
        asm volatile("{ .reg .pred P1; WL_%=: mbarrier.try_wait.parity.acquire.cta.shared::cta.b64 P1, [%0], %1, 0x989680; @P1 bra.uni WD_%=; bra.uni WL_%=; WD_%=: }" \
            :: "r"(_m), "r"(_p) : "memory");                                      \
    }                                                                             \
} while (0)
#define BULK_G2S(dst, src, bytes, mbar)                                           \
    asm volatile("cp.async.bulk.shared::cluster.global.mbarrier::complete_tx::bytes [%0], [%1], %2, [%3];" \
        :: "r"(dst), "l"(src), "r"((uint32_t)(bytes)), "r"(mbar) : "memory")

__device__ __forceinline__ uint32_t pack2h(__half a, __half b) {
    __half2 t = __halves2half2(a, b);
    return *reinterpret_cast<uint32_t*>(&t);
}

// ---------------------------------------------------------------- routing
__global__ void route_kernel(const int* __restrict__ eidx, const float* __restrict__ prob) {
    __shared__ int s_cnt[NE];
    const int tid = threadIdx.x;
    if (tid < NE) s_cnt[tid] = 0;
    __syncthreads();
    for (int p = tid; p < NP; p += blockDim.x) atomicAdd(&s_cnt[eidx[p]], 1);
    __syncthreads();
    if (tid == 0) {
        int start = 0;
        for (int e = 0; e < NE; e++) {
            g_count[e] = s_cnt[e]; g_off[e] = start; g_fill[e] = start;
            start += (s_cnt[e] + 255) & ~255;   // 256-aligned segments
        }
    }
    for (int i = tid; i < NPPAD; i += blockDim.x) { g_tok[i] = 0; g_coef[i] = 0.f; }
    __syncthreads();
    for (int p = tid; p < NP; p += blockDim.x) {
        const int e = eidx[p];
        const int pos = atomicAdd(&g_fill[e], 1);
        const float df = (p & 1) ? 0.25f : 0.5f;
        g_pairpos[p] = pos;
        g_tok[pos]   = p >> 1;
        g_coef[pos]  = df * prob[p];
    }
}

// ------------------------- gather activations -> fp16, tiled+swizzled blocks
__global__ void split_x_kernel(const float* __restrict__ X) {
    const int i = blockIdx.x * 256 + threadIdx.x;       // over NPPAD * (DM/4)
    if (i >= NPPAD * (DM / 4)) return;
    const int row = i / (DM / 4);
    const int c4  = i % (DM / 4);                       // 16B unit in source row
    const float4 v = reinterpret_cast<const float4*>(X + (size_t)g_tok[row] * DM)[c4];
    const uint2 o = make_uint2(pack2h(__float2half(v.x), __float2half(v.y)),
                               pack2h(__float2half(v.z), __float2half(v.w)));
    const int blk = row >> 8, rowin = row & 255;
    const int ch  = c4 >> 4;                            // 64-col chunk
    const uint32_t byte = SWZ((uint32_t)(rowin * 128 + (c4 & 15) * 8));
    *reinterpret_cast<uint2*>(g_Xg + ((size_t)blk * 8 + ch) * ABLK + byte) = o;
}

// --------- transpose + scale(x64) weights -> tiled+swizzled blocks (fp16)
// src [e][R][C] fp32 -> [e][n/128][k/64][SWZ((n%128)*128 + (k%64)*2)]
__global__ void transpose_split_kernel(const float* __restrict__ src, int R, int C, int which) {
    unsigned char* dst = which ? g_woT : g_wiT;
    const int e = blockIdx.z;
    const int NBLKn = C / 128, NCHk = R / 64;
    const float* s = src + (size_t)e * R * C;

    __shared__ float t[64][65];
    const int c0 = blockIdx.x * 64, r0 = blockIdx.y * 64;
    const int tid = threadIdx.x;

    const int lr = tid >> 4;          // 0..15
    const int lc = (tid & 15) * 4;    // 0..60
#pragma unroll
    for (int it = 0; it < 4; it++) {
        const int r = it * 16 + lr;
        const float4 v = *reinterpret_cast<const float4*>(s + (size_t)(r0 + r) * C + c0 + lc);
        t[lc + 0][r] = v.x; t[lc + 1][r] = v.y; t[lc + 2][r] = v.z; t[lc + 3][r] = v.w;
    }
    __syncthreads();

    const int oc = tid >> 2;          // 0..63  (output n within 64-tile)
    const int rs = (tid & 3) * 16;    // k start 0,16,32,48
    uint32_t hw[8];
#pragma unroll
    for (int q = 0; q < 8; q++) {
        const float v0 = t[oc][rs + 2 * q]     * WSCALE;
        const float v1 = t[oc][rs + 2 * q + 1] * WSCALE;
        hw[q] = pack2h(__float2half(v0), __float2half(v1));
    }
    const int n = c0 + oc, k = r0 + rs;
    const size_t boff = (((size_t)e * NBLKn + (n >> 7)) * NCHk + (k >> 6)) * BBLK;
    const int nin = n & 127, kin = k & 63;
    const uint32_t b0 = SWZ((uint32_t)(nin * 128 + kin * 2));
    const uint32_t b1 = SWZ((uint32_t)(nin * 128 + kin * 2 + 16));
    *reinterpret_cast<uint4*>(dst + boff + b0) = make_uint4(hw[0], hw[1], hw[2], hw[3]);
    *reinterpret_cast<uint4*>(dst + boff + b1) = make_uint4(hw[4], hw[5], hw[6], hw[7]);
}

// ------------------------------------------------- HMMA GEMM (both layers)
// MODE 0: H = relu(Xg @ wiT'^T)/64      [K=DM, N=DF] -> fp16 tiled blocks
// MODE 1: Y = (coef/64) * (H @ woT'^T)  [K=DF, N=DM] -> fp32
// Single fp16 weight limb. CTA: 128 M x 128 N, 8 warps 4(M)x2(N), warp 32x64.
// 2 CTAs/SM; bulk-async loads of pre-swizzled blocks, mbarrier-paced, 3 stages.
template <int MODE>
__global__ __launch_bounds__(256, 2)
void gemm_mma() {
    constexpr int NC = (MODE == 0) ? (DM / 64) : (DF / 64);

    const int e = blockIdx.z;
    const int cnt = g_count[e];
    const int mbase = blockIdx.y * 128;
    if (mbase >= cnt) return;
    const int off = g_off[e];
    const int nbase = blockIdx.x * 128;
    const int tid = threadIdx.x;
    const int lid = tid & 31;
    const int wid = tid >> 5;
    const int wm = wid >> 1;      // 0..3 -> 32-row slab
    const int wn = wid & 1;       // 0..1 -> 64-col slab

    extern __shared__ char dynsmem[];
    const uint32_t raw  = smem_u32(dynsmem);
    const uint32_t base = (raw + 1023) & ~1023u;
    __shared__ __align__(8) uint64_t s_mbar[NSTAGE];
    uint32_t mb[NSTAGE];
#pragma unroll
    for (int s = 0; s < NSTAGE; s++) mb[s] = smem_u32(&s_mbar[s]);

    if (tid == 0) {
#pragma unroll
        for (int s = 0; s < NSTAGE; s++) MBAR_INIT(mb[s], 1);
    }
    __syncthreads();

    const int ablk = (off + mbase) >> 8;          // 256-row storage block
    const int half = (mbase >> 7) & 1;            // which 128-row half (off is 256-aligned)
    const unsigned char* Asrc = ((MODE == 0)
        ? (g_Xg + (size_t)ablk * 8  * ABLK)
        : (g_H  + (size_t)ablk * 32 * ABLK)) + (size_t)half * AHALF;
    const unsigned char* Bsrc = (MODE == 0)
        ? (g_wiT + (((size_t)e * 16 + (nbase >> 7)) * 8)  * BBLK)
        : (g_woT + (((size_t)e * 4  + (nbase >> 7)) * 32) * BBLK);

    auto issue = [&](int c) {
        const int st = c % NSTAGE;
        const uint32_t m = mb[st];
        const uint32_t tb = base + st * STAGE_BYTES;
        MBAR_EXPECT_TX(m, STAGE_BYTES);
        BULK_G2S(tb,         Asrc + (size_t)c * ABLK, AHALF, m);
        BULK_G2S(tb + AHALF, Bsrc + (size_t)c * BBLK, BBLK, m);
    };

    float acc[2][8][4];
#pragma unroll
    for (int f = 0; f < 2; f++)
#pragma unroll
        for (int j = 0; j < 8; j++)
#pragma unroll
            for (int q = 0; q < 4; q++) acc[f][j][q] = 0.f;

    const int bq  = (lid & 7) | ((lid >> 4) << 3);   // B: n row within 16-group
    const int bkh = ((lid >> 3) & 1) * 16;           // B: k-half byte offset
    const int ar  = lid & 15;                        // A: m row within 16-group
    const int akh = (lid >> 4) * 16;                 // A: k-half byte offset

    if (tid == 0) { issue(0); issue(1); issue(2); }  // NC >= 8 always

    for (int c = 0; c < NC; c++) {
        const int st = c % NSTAGE;
        MBAR_WAIT(mb[st], (c / NSTAGE) & 1);

        const uint32_t tb = base + st * STAGE_BYTES;
        const uint32_t pA = tb;
        const uint32_t pB = tb + AHALF;

#pragma unroll
        for (int s = 0; s < 4; s++) {
            const int kb = s * 32;                   // byte offset of k16 step
            uint32_t bh[8][2];
#pragma unroll
            for (int P = 0; P < 4; P++) {            // 64 n-cols = 4 x 16 rows
                const uint32_t a = SWZ((wn * 64 + P * 16 + bq) * 128 + kb + bkh);
                LDSM4(bh[2 * P][0], bh[2 * P][1], bh[2 * P + 1][0], bh[2 * P + 1][1], pB + a);
            }
#pragma unroll
            for (int f = 0; f < 2; f++) {
                uint32_t av[4];
                const uint32_t a = SWZ((wm * 32 + f * 16 + ar) * 128 + kb + akh);
                LDSM4(av[0], av[1], av[2], av[3], pA + a);
#pragma unroll
                for (int j = 0; j < 8; j++) mma16816(acc[f][j], av, bh[j]);
            }
        }
        __syncthreads();                      // all warps done with stage st
        if (tid == 0 && c + NSTAGE < NC) issue(c + NSTAGE);
    }

    // ------------------------------------------------------------ epilogue
#pragma unroll
    for (int f = 0; f < 2; f++) {
        const int rib0 = wm * 32 + f * 16 + (lid >> 2);      // row in 128-tile
#pragma unroll
        for (int h = 0; h < 2; h++) {
            const int rib = rib0 + h * 8;
            const int r = mbase + rib;
            if (r < cnt) {
                if (MODE == 0) {
                    // H tiled: [ablk][col/64][SWZ(rib256*128 + (col%64)*2)]
                    const int ch = (nbase >> 6) + wn;
                    const int rib256 = half * 128 + rib;
                    unsigned char* Hb = g_H + ((size_t)ablk * 32 + ch) * ABLK;
#pragma unroll
                    for (int j = 0; j < 8; j++) {
                        const float v0 = fmaxf(acc[f][j][2 * h], 0.f) * INV_WSCALE;
                        const float v1 = fmaxf(acc[f][j][2 * h + 1], 0.f) * INV_WSCALE;
                        const uint32_t byte = SWZ((uint32_t)(rib256 * 128 + (lid & 3) * 4 + j * 16));
                        *reinterpret_cast<uint32_t*>(Hb + byte) = pack2h(__float2half(v0), __float2half(v1));
                    }
                } else {
                    const float cf = g_coef[off + r] * INV_WSCALE;
                    const int colb = nbase + wn * 64 + (lid & 3) * 2;
                    float* Yp = g_Y + (size_t)(off + r) * DM + colb;
#pragma unroll
                    for (int j = 0; j < 8; j++) {
                        float2 v;
                        v.x = cf * acc[f][j][2 * h];
                        v.y = cf * acc[f][j][2 * h + 1];
                        *reinterpret_cast<float2*>(Yp + j * 8) = v;
                    }
                }
            }
        }
    }
}

// ---------------------------------------------------- finalize: combine + where
__global__ void finalize_kernel(const float* __restrict__ X, float* __restrict__ out) {
    const int i = blockIdx.x * blockDim.x + threadIdx.x;
    if (i >= NT * DM / 4) return;
    const int t = i / (DM / 4);
    const int d4 = i % (DM / 4);
    const int p0 = g_pairpos[2 * t];
    const int p1 = g_pairpos[2 * t + 1];
    const float4 y0 = *reinterpret_cast<const float4*>(g_Y + (size_t)p0 * DM + d4 * 4);
    const float4 y1 = *reinterpret_cast<const float4*>(g_Y + (size_t)p1 * DM + d4 * 4);
    const float4 xv = reinterpret_cast<const float4*>(X)[i];
    float4 s, o;
    s.x = y0.x + y1.x; s.y = y0.y + y1.y; s.z = y0.z + y1.z; s.w = y0.w + y1.w;
    o.x = (s.x != 0.f) ? s.x : xv.x;
    o.y = (s.y != 0.f) ? s.y : xv.y;
    o.z = (s.z != 0.f) ? s.z : xv.z;
    o.w = (s.w != 0.f) ? s.w : xv.w;
    reinterpret_cast<float4*>(out)[i] = o;
}

extern "C" void kernel_launch(void* const* d_in, const int* in_sizes, int n_in,
                              void* d_out, int out_size) {
    const float* hs   = (const float*)d_in[0];   // [4096, 512]
    const float* prob = (const float*)d_in[1];   // [4096, 2]
    const float* wi   = (const float*)d_in[2];   // [8, 512, 2048]
    const float* wo   = (const float*)d_in[3];   // [8, 2048, 512]
    const int*   eidx = (const int*)d_in[4];     // [4096, 2]
    float* out = (float*)d_out;

    const int SMEM = NSTAGE * STAGE_BYTES + 1024;   // 99328 B (2 CTAs/SM)
    cudaFuncSetAttribute(gemm_mma<0>, cudaFuncAttributeMaxDynamicSharedMemorySize, SMEM);
    cudaFuncSetAttribute(gemm_mma<1>, cudaFuncAttributeMaxDynamicSharedMemorySize, SMEM);

    route_kernel<<<1, 256>>>(eidx, prob);
    split_x_kernel<<<(NPPAD * (DM / 4) + 255) / 256, 256>>>(hs);
    transpose_split_kernel<<<dim3(DF / 64, DM / 64, NE), 256>>>(wi, DM, DF, 0);
    transpose_split_kernel<<<dim3(DM / 64, DF / 64, NE), 256>>>(wo, DF, DM, 1);

    gemm_mma<0><<<dim3(DF / 128, NPPAD / 128, NE), 256, SMEM>>>();
    gemm_mma<1><<<dim3(DM / 128, NPPAD / 128, NE), 256, SMEM>>>();

    finalize_kernel<<<(NT * DM / 4 + 255) / 256, 256>>>(hs, out);
}